// round 1
// baseline (speedup 1.0000x reference)
#include <cuda_runtime.h>

// ---------------------------------------------------------------------------
// Problem constants
// ---------------------------------------------------------------------------
#define NG 16            // 8 batches x 2 element classes
#define NC 8192          // 32*32*8 cells per group
#define NB 8             // batches
#define LATX 0.78125f    // 25/32 (exact)
#define LATY 0.78125f
#define LATZ 0.375f      // 3/8 (exact)

// diam per element class, computed in double then rounded to fp32 like JAX
#define DIAM0 ((float)(0.74 * 1.4))
#define DIAM1 ((float)(0.528 * 1.4))

// ---------------------------------------------------------------------------
// Device scratch (no allocations allowed)
// ---------------------------------------------------------------------------
__device__ float g_ppos[NG][NC][3];   // masked pred positions (scan order)
__device__ float g_praw[NG][NC][4];   // masked pred raw rows
__device__ float g_pconf[NG][NC];     // masked pred confidences
__device__ float g_qp[NG][NC];        // squared norms of ppos
__device__ float g_tpos[NG][NC][3];   // masked target positions
__device__ float g_traw[NG][NC][4];
__device__ float g_qt[NG][NC];

__device__ float g_sp[NG][NC][3];     // ppos sorted by ascending conf (stable)
__device__ float g_sq[NG][NC];
__device__ int   g_sidx[NG][NC];      // sorted -> compact index

__device__ unsigned char g_res0[NG][NC];  // restrain[i] == 0 flag (sorted order)
__device__ unsigned char g_keep[NG][NC];  // sel flag (sorted order)

__device__ float g_npos[NG][NC][3];   // NMS-kept positions (sorted order, compact)
__device__ float g_nq[NG][NC];
__device__ int   g_nsrc[NG][NC];      // kept -> compact pred index

__device__ int g_m[NG][NC];           // target matched (full preds)
__device__ int g_piv[NG][NC];         // argmin pred index
__device__ int g_mn[NG][NC];          // target matched (nms preds)
__device__ int g_pinv[NG][NC];

__device__ int g_ti[NG][NC], g_pi[NG][NC], g_tin[NG][NC], g_pin[NG][NC];

__device__ int g_np[NG], g_nt[NG], g_nn[NG], g_k[NG], g_kn[NG];
__device__ long long g_base[NG];

// ---------------------------------------------------------------------------
// Distance exactly mirroring the JAX cdist:
//   aa = x*x + y*y + z*z      (elementwise mul, linear reduce, NO fma)
//   ab = dot(a,b)             (fma-accumulated K-loop)
//   s  = (aa + bb) - 2*ab ; d = sqrt(max(s, 0))
// All ops as explicit intrinsics so ptxas cannot re-contract.
// ---------------------------------------------------------------------------
__device__ __forceinline__ float sqnorm3(float x, float y, float z) {
    return __fadd_rn(__fadd_rn(__fmul_rn(x, x), __fmul_rn(y, y)), __fmul_rn(z, z));
}

__device__ __forceinline__ float distf(float qi, float qj,
                                       float xi, float yi, float zi,
                                       float xj, float yj, float zj) {
    float ab = __fmul_rn(xi, xj);
    ab = fmaf(yi, yj, ab);
    ab = fmaf(zi, zj, ab);
    float s = __fsub_rn(__fadd_rn(qi, qj), __fmul_rn(2.0f, ab));
    return sqrtf(fmaxf(s, 0.0f));
}

// ---------------------------------------------------------------------------
// K1: per-group masking + stable compaction (scan order) for preds & targets
// ---------------------------------------------------------------------------
__global__ void k_compact(const float* __restrict__ pred,
                          const float* __restrict__ tgt) {
    int g = blockIdx.x;
    int b = g >> 1, e = g & 1;
    int tid = threadIdx.x;
    int lane = tid & 31, w = tid >> 5;

    __shared__ int wtp[8], wtt[8];
    __shared__ int basep, baset;
    if (tid == 0) { basep = 0; baset = 0; }
    __syncthreads();

    for (int cb = 0; cb < NC; cb += 256) {
        int cell = cb + tid;                 // NC % 256 == 0 -> always valid
        int i = cell >> 8;
        int j = (cell >> 3) & 31;
        int k = cell & 7;
        int inIdx = ((((b * 32 + i) * 32 + j) * 8 + k) * 2 + e) * 4;

        float p0 = pred[inIdx + 0], p1 = pred[inIdx + 1];
        float p2 = pred[inIdx + 2], p3 = pred[inIdx + 3];
        float t0 = tgt[inIdx + 0],  t1 = tgt[inIdx + 1];
        float t2 = tgt[inIdx + 2],  t3 = tgt[inIdx + 3];

        int mp = p3 > 0.5f;
        int mt = t3 > 0.5f;
        unsigned bp = __ballot_sync(0xffffffffu, mp);
        unsigned bt = __ballot_sync(0xffffffffu, mt);
        if (lane == 0) { wtp[w] = __popc(bp); wtt[w] = __popc(bt); }
        __syncthreads();

        int offp = basep, offt = baset;
        for (int x = 0; x < w; x++) { offp += wtp[x]; offt += wtt[x]; }
        offp += __popc(bp & ((1u << lane) - 1u));
        offt += __popc(bt & ((1u << lane) - 1u));

        if (mp) {
            float px = __fmul_rn(__fadd_rn(p0, (float)i), LATX);
            float py = __fmul_rn(__fadd_rn(p1, (float)j), LATY);
            float pz = __fmul_rn(__fadd_rn(p2, (float)k), LATZ);
            g_praw[g][offp][0] = p0; g_praw[g][offp][1] = p1;
            g_praw[g][offp][2] = p2; g_praw[g][offp][3] = p3;
            g_ppos[g][offp][0] = px; g_ppos[g][offp][1] = py; g_ppos[g][offp][2] = pz;
            g_pconf[g][offp] = p3;
            g_qp[g][offp] = sqnorm3(px, py, pz);
        }
        if (mt) {
            float tx = __fmul_rn(__fadd_rn(t0, (float)i), LATX);
            float ty = __fmul_rn(__fadd_rn(t1, (float)j), LATY);
            float tz = __fmul_rn(__fadd_rn(t2, (float)k), LATZ);
            g_traw[g][offt][0] = t0; g_traw[g][offt][1] = t1;
            g_traw[g][offt][2] = t2; g_traw[g][offt][3] = t3;
            g_tpos[g][offt][0] = tx; g_tpos[g][offt][1] = ty; g_tpos[g][offt][2] = tz;
            g_qt[g][offt] = sqnorm3(tx, ty, tz);
        }
        __syncthreads();
        if (tid == 0) {
            int sp_ = 0, st_ = 0;
            for (int x = 0; x < 8; x++) { sp_ += wtp[x]; st_ += wtt[x]; }
            basep += sp_; baset += st_;
        }
        __syncthreads();
    }
    if (tid == 0) { g_np[g] = basep; g_nt[g] = baset; }
}

// ---------------------------------------------------------------------------
// K2: stable ascending argsort by confidence via O(N^2) rank counting
// ---------------------------------------------------------------------------
__global__ void k_rank() {
    int g = blockIdx.y;
    int i = blockIdx.x * blockDim.x + threadIdx.x;
    int Np = g_np[g];
    if (i >= Np) return;
    float ci = g_pconf[g][i];
    int rank = 0;
    for (int j = 0; j < Np; j++) {
        float cj = g_pconf[g][j];
        rank += (int)((cj < ci) | ((cj == ci) & (j < i)));
    }
    g_sp[g][rank][0] = g_ppos[g][i][0];
    g_sp[g][rank][1] = g_ppos[g][i][1];
    g_sp[g][rank][2] = g_ppos[g][i][2];
    g_sq[g][rank]    = g_qp[g][i];
    g_sidx[g][rank]  = i;
}

// ---------------------------------------------------------------------------
// K3: restrain[j] == 0 flag: no i<j (sorted) within diam. Early exit.
// ---------------------------------------------------------------------------
__global__ void k_restrain() {
    int g = blockIdx.y;
    int j = blockIdx.x * blockDim.x + threadIdx.x;
    int Np = g_np[g];
    if (j >= Np) return;
    float diam = (g & 1) ? DIAM1 : DIAM0;
    float xj = g_sp[g][j][0], yj = g_sp[g][j][1], zj = g_sp[g][j][2];
    float qj = g_sq[g][j];
    int hit = 0;
    for (int i = 0; i < j; i++) {
        float d = distf(g_sq[g][i], qj,
                        g_sp[g][i][0], g_sp[g][i][1], g_sp[g][i][2], xj, yj, zj);
        if (d < diam) { hit = 1; break; }
    }
    g_res0[g][j] = (unsigned char)(!hit);
}

// ---------------------------------------------------------------------------
// K4: sel[j]: no i<j within diam having restrain[i]==0. Early exit.
// ---------------------------------------------------------------------------
__global__ void k_sel() {
    int g = blockIdx.y;
    int j = blockIdx.x * blockDim.x + threadIdx.x;
    int Np = g_np[g];
    if (j >= Np) return;
    float diam = (g & 1) ? DIAM1 : DIAM0;
    float xj = g_sp[g][j][0], yj = g_sp[g][j][1], zj = g_sp[g][j][2];
    float qj = g_sq[g][j];
    int bad = 0;
    for (int i = 0; i < j; i++) {
        if (!g_res0[g][i]) continue;
        float d = distf(g_sq[g][i], qj,
                        g_sp[g][i][0], g_sp[g][i][1], g_sp[g][i][2], xj, yj, zj);
        if (d < diam) { bad = 1; break; }
    }
    g_keep[g][j] = (unsigned char)(!bad);
}

// ---------------------------------------------------------------------------
// K5: compact kept (sorted order) -> g_npos/g_nsrc, count Nn
// ---------------------------------------------------------------------------
__global__ void k_nms_compact() {
    int g = blockIdx.x;
    int tid = threadIdx.x;
    int lane = tid & 31, w = tid >> 5;
    int Np = g_np[g];
    __shared__ int wt[8];
    __shared__ int base;
    if (tid == 0) base = 0;
    __syncthreads();
    for (int cb = 0; cb < Np; cb += 256) {
        int j = cb + tid;
        int f = (j < Np) ? (int)g_keep[g][j] : 0;
        unsigned bl = __ballot_sync(0xffffffffu, f);
        if (lane == 0) wt[w] = __popc(bl);
        __syncthreads();
        int off = base;
        for (int x = 0; x < w; x++) off += wt[x];
        off += __popc(bl & ((1u << lane) - 1u));
        if (f) {
            g_npos[g][off][0] = g_sp[g][j][0];
            g_npos[g][off][1] = g_sp[g][j][1];
            g_npos[g][off][2] = g_sp[g][j][2];
            g_nq[g][off]      = g_sq[g][j];
            g_nsrc[g][off]    = g_sidx[g][j];
        }
        __syncthreads();
        if (tid == 0) { int s = 0; for (int x = 0; x < 8; x++) s += wt[x]; base += s; }
        __syncthreads();
    }
    if (tid == 0) g_nn[g] = base;
}

// ---------------------------------------------------------------------------
// K6: match each target vs full preds and vs NMS preds (argmin = first min)
// ---------------------------------------------------------------------------
__global__ void k_match() {
    int g = blockIdx.y;
    int t = blockIdx.x * blockDim.x + threadIdx.x;
    int Nt = g_nt[g];
    if (t >= Nt) return;
    float diam = (g & 1) ? DIAM1 : DIAM0;
    float tx = g_tpos[g][t][0], ty = g_tpos[g][t][1], tz = g_tpos[g][t][2];
    float qt = g_qt[g][t];

    int Np = g_np[g];
    float best = 3.4e38f; int bi = 0; int any = 0;
    for (int j = 0; j < Np; j++) {
        float d = distf(qt, g_qp[g][j], tx, ty, tz,
                        g_ppos[g][j][0], g_ppos[g][j][1], g_ppos[g][j][2]);
        any |= (d < diam);
        if (d < best) { best = d; bi = j; }
    }
    g_m[g][t] = any; g_piv[g][t] = bi;

    int Nn = g_nn[g];
    best = 3.4e38f; bi = 0; any = 0;
    for (int j = 0; j < Nn; j++) {
        float d = distf(qt, g_nq[g][j], tx, ty, tz,
                        g_npos[g][j][0], g_npos[g][j][1], g_npos[g][j][2]);
        any |= (d < diam);
        if (d < best) { best = d; bi = j; }
    }
    g_mn[g][t] = any; g_pinv[g][t] = bi;
}

// ---------------------------------------------------------------------------
// K7: compact (ti, pi) and (ti_n, pi_n)
// ---------------------------------------------------------------------------
__global__ void k_match_compact() {
    int g = blockIdx.x;
    int tid = threadIdx.x;
    int lane = tid & 31, w = tid >> 5;
    int Nt = g_nt[g];
    __shared__ int wt[8];
    __shared__ int base;

    // pass 0: full match; pass 1: nms match
    for (int pass = 0; pass < 2; pass++) {
        if (tid == 0) base = 0;
        __syncthreads();
        for (int cb = 0; cb < Nt; cb += 256) {
            int t = cb + tid;
            int f = 0;
            if (t < Nt) f = pass ? g_mn[g][t] : g_m[g][t];
            unsigned bl = __ballot_sync(0xffffffffu, f != 0);
            if (lane == 0) wt[w] = __popc(bl);
            __syncthreads();
            int off = base;
            for (int x = 0; x < w; x++) off += wt[x];
            off += __popc(bl & ((1u << lane) - 1u));
            if (f) {
                if (pass) { g_tin[g][off] = t; g_pin[g][off] = g_pinv[g][t]; }
                else      { g_ti[g][off]  = t; g_pi[g][off]  = g_piv[g][t]; }
            }
            __syncthreads();
            if (tid == 0) { int s = 0; for (int x = 0; x < 8; x++) s += wt[x]; base += s; }
            __syncthreads();
        }
        if (tid == 0) { if (pass) g_kn[g] = base; else g_k[g] = base; }
        __syncthreads();
    }
}

// ---------------------------------------------------------------------------
// K8: per-group output base offsets (output is one flat fp32 stream)
// ---------------------------------------------------------------------------
__global__ void k_offsets() {
    long long base = 0;
    for (int g = 0; g < NG; g++) {
        g_base[g] = base;
        long long Np = g_np[g], Nn = g_nn[g], Nt = g_nt[g], K = g_k[g], Kn = g_kn[g];
        base += Np * 4 + Nn * 4 + Nt * 4 + 2 * K + 2 * Kn + Np * 3 + Nn * 3 + Nt * 3;
    }
}

// ---------------------------------------------------------------------------
// K9: write the concatenated output
// order per group: pred[mp](Np,4), pnms(Nn,4), tgt[mt](Nt,4),
//                  ti(K), pi(K), ti_n(Kn), pi_n(Kn),
//                  ppos(Np,3), ppos_nms(Nn,3), tpos(Nt,3)
// ---------------------------------------------------------------------------
__global__ void k_write(float* __restrict__ out) {
    int g = blockIdx.y;
    long long base = g_base[g];
    int Np = g_np[g], Nn = g_nn[g], Nt = g_nt[g], K = g_k[g], Kn = g_kn[g];
    int T = Np * 4 + Nn * 4 + Nt * 4 + 2 * K + 2 * Kn + Np * 3 + Nn * 3 + Nt * 3;
    int stride = gridDim.x * blockDim.x;
    for (int idx = blockIdx.x * blockDim.x + threadIdx.x; idx < T; idx += stride) {
        int o = idx;
        float v;
        if (o < Np * 4) { v = g_praw[g][o >> 2][o & 3]; }
        else {
            o -= Np * 4;
            if (o < Nn * 4) { v = g_praw[g][g_nsrc[g][o >> 2]][o & 3]; }
            else {
                o -= Nn * 4;
                if (o < Nt * 4) { v = g_traw[g][o >> 2][o & 3]; }
                else {
                    o -= Nt * 4;
                    if (o < K) { v = (float)g_ti[g][o]; }
                    else {
                        o -= K;
                        if (o < K) { v = (float)g_pi[g][o]; }
                        else {
                            o -= K;
                            if (o < Kn) { v = (float)g_tin[g][o]; }
                            else {
                                o -= Kn;
                                if (o < Kn) { v = (float)g_pin[g][o]; }
                                else {
                                    o -= Kn;
                                    if (o < Np * 3) { v = g_ppos[g][o / 3][o % 3]; }
                                    else {
                                        o -= Np * 3;
                                        if (o < Nn * 3) { v = g_npos[g][o / 3][o % 3]; }
                                        else { o -= Nn * 3; v = g_tpos[g][o / 3][o % 3]; }
                                    }
                                }
                            }
                        }
                    }
                }
            }
        }
        out[base + idx] = v;
    }
}

// ---------------------------------------------------------------------------
// launch
// ---------------------------------------------------------------------------
extern "C" void kernel_launch(void* const* d_in, const int* in_sizes, int n_in,
                              void* d_out, int out_size) {
    const float* pred = (const float*)d_in[0];
    const float* tgt  = (const float*)d_in[1];
    float* out = (float*)d_out;
    (void)in_sizes; (void)n_in; (void)out_size;

    dim3 gidx(32, NG);   // 32*256 = 8192 threads per group

    k_compact<<<NG, 256>>>(pred, tgt);
    k_rank<<<gidx, 256>>>();
    k_restrain<<<gidx, 256>>>();
    k_sel<<<gidx, 256>>>();
    k_nms_compact<<<NG, 256>>>();
    k_match<<<gidx, 256>>>();
    k_match_compact<<<NG, 256>>>();
    k_offsets<<<1, 1>>>();
    k_write<<<gidx, 256>>>(out);
}

// round 2
// speedup vs baseline: 8.1181x; 8.1181x over previous
#include <cuda_runtime.h>

#define NG 16            // 8 batches x 2 element classes
#define NC 8192          // 32*32*8 cells per group
#define LATX 0.78125f    // 25/32 exact
#define LATY 0.78125f
#define LATZ 0.375f      // 3/8 exact
#define DIAM0 ((float)(0.74 * 1.4))
#define DIAM1 ((float)(0.528 * 1.4))
#define MAXCELLS 4608    // >= 33*33*4

// ---------------------------------------------------------------------------
// Device scratch
// ---------------------------------------------------------------------------
__device__ float g_ppos[NG][NC][3];
__device__ float g_praw[NG][NC][4];
__device__ float g_qp[NG][NC];
__device__ unsigned long long g_key[NG][NC];  // (conf bits << 32) | maskedIdx
__device__ float g_tpos[NG][NC][3];
__device__ float g_traw[NG][NC][4];
__device__ float g_qt[NG][NC];

__device__ int g_pc[NG][NC];                  // pred cell id
__device__ int g_cstart[NG][MAXCELLS + 1];
__device__ int g_clist[NG][NC];

__device__ unsigned char g_res0[NG][NC];      // restrain==0 flag (by masked idx)
__device__ unsigned char g_keep[NG][NC];      // sel flag (by masked idx)

__device__ unsigned long long g_kkey[NG][NC]; // kept keys pre-sort
__device__ int g_nk[NG];

__device__ float g_npos[NG][NC][3];           // kept, sorted by key ascending
__device__ float g_nq[NG][NC];
__device__ int   g_nsrc[NG][NC];              // sorted kept -> masked idx
__device__ int g_kc[NG][NC];
__device__ int g_kstart[NG][MAXCELLS + 1];
__device__ int g_klist[NG][NC];

__device__ int g_m[NG][NC], g_piv[NG][NC], g_mn[NG][NC], g_pinv[NG][NC];
__device__ int g_ti[NG][NC], g_pi[NG][NC], g_tin[NG][NC], g_pin[NG][NC];
__device__ int g_np[NG], g_nt[NG], g_nn[NG], g_k[NG], g_kn[NG];
__device__ long long g_base[NG];

// ---------------------------------------------------------------------------
// Helpers
// ---------------------------------------------------------------------------
__device__ __forceinline__ void gdims(int e, int& CX, int& CY, int& CZ) {
    if (e) { CX = 33; CY = 33; CZ = 4; } else { CX = 24; CY = 24; CZ = 2; }
}

__device__ __forceinline__ float sqnorm3(float x, float y, float z) {
    return __fadd_rn(__fadd_rn(__fmul_rn(x, x), __fmul_rn(y, y)), __fmul_rn(z, z));
}

// s = (qi+qj) - 2*dot, exactly mirroring JAX (add commutes bit-exactly)
__device__ __forceinline__ float dist2(float qi, float qj,
                                       float xi, float yi, float zi,
                                       float xj, float yj, float zj) {
    float ab = __fmul_rn(xi, xj);
    ab = fmaf(yi, yj, ab);
    ab = fmaf(zi, zj, ab);
    return __fsub_rn(__fadd_rn(qi, qj), __fmul_rn(2.0f, ab));
}

// Smallest float S with sqrtf(S) >= D, calibrated against device sqrtf.
// Then rn(sqrt(max(s,0))) < D  <=>  s < S   (monotone; s<0 => both true).
__device__ __forceinline__ float sqr_thresh(float D) {
    float s = __fmul_rn(D, D);
    while (sqrtf(s) < D) s = __uint_as_float(__float_as_uint(s) + 1u);
    for (;;) {
        float sm = __uint_as_float(__float_as_uint(s) - 1u);
        if (sqrtf(sm) >= D) s = sm; else break;
    }
    return s;
}

// ---------------------------------------------------------------------------
// K1: masking + stable compaction
// ---------------------------------------------------------------------------
__global__ void k_compact(const float* __restrict__ pred,
                          const float* __restrict__ tgt) {
    int g = blockIdx.x;
    int b = g >> 1, e = g & 1;
    int tid = threadIdx.x;
    int lane = tid & 31, w = tid >> 5;

    __shared__ int wtp[8], wtt[8];
    __shared__ int basep, baset;
    if (tid == 0) { basep = 0; baset = 0; }
    __syncthreads();

    for (int cb = 0; cb < NC; cb += 256) {
        int cell = cb + tid;
        int i = cell >> 8;
        int j = (cell >> 3) & 31;
        int k = cell & 7;
        int inIdx = ((((b * 32 + i) * 32 + j) * 8 + k) * 2 + e) * 4;

        float p0 = pred[inIdx + 0], p1 = pred[inIdx + 1];
        float p2 = pred[inIdx + 2], p3 = pred[inIdx + 3];
        float t0 = tgt[inIdx + 0],  t1 = tgt[inIdx + 1];
        float t2 = tgt[inIdx + 2],  t3 = tgt[inIdx + 3];

        int mp = p3 > 0.5f;
        int mt = t3 > 0.5f;
        unsigned bp = __ballot_sync(0xffffffffu, mp);
        unsigned bt = __ballot_sync(0xffffffffu, mt);
        if (lane == 0) { wtp[w] = __popc(bp); wtt[w] = __popc(bt); }
        __syncthreads();

        int offp = basep, offt = baset;
        for (int x = 0; x < w; x++) { offp += wtp[x]; offt += wtt[x]; }
        offp += __popc(bp & ((1u << lane) - 1u));
        offt += __popc(bt & ((1u << lane) - 1u));

        if (mp) {
            float px = __fmul_rn(__fadd_rn(p0, (float)i), LATX);
            float py = __fmul_rn(__fadd_rn(p1, (float)j), LATY);
            float pz = __fmul_rn(__fadd_rn(p2, (float)k), LATZ);
            g_praw[g][offp][0] = p0; g_praw[g][offp][1] = p1;
            g_praw[g][offp][2] = p2; g_praw[g][offp][3] = p3;
            g_ppos[g][offp][0] = px; g_ppos[g][offp][1] = py; g_ppos[g][offp][2] = pz;
            g_qp[g][offp] = sqnorm3(px, py, pz);
            g_key[g][offp] = ((unsigned long long)__float_as_uint(p3) << 32) | (unsigned)offp;
        }
        if (mt) {
            float tx = __fmul_rn(__fadd_rn(t0, (float)i), LATX);
            float ty = __fmul_rn(__fadd_rn(t1, (float)j), LATY);
            float tz = __fmul_rn(__fadd_rn(t2, (float)k), LATZ);
            g_traw[g][offt][0] = t0; g_traw[g][offt][1] = t1;
            g_traw[g][offt][2] = t2; g_traw[g][offt][3] = t3;
            g_tpos[g][offt][0] = tx; g_tpos[g][offt][1] = ty; g_tpos[g][offt][2] = tz;
            g_qt[g][offt] = sqnorm3(tx, ty, tz);
        }
        __syncthreads();
        if (tid == 0) {
            int sp_ = 0, st_ = 0;
            for (int x = 0; x < 8; x++) { sp_ += wtp[x]; st_ += wtt[x]; }
            basep += sp_; baset += st_;
        }
        __syncthreads();
    }
    if (tid == 0) { g_np[g] = basep; g_nt[g] = baset; }
}

// ---------------------------------------------------------------------------
// K2: build spatial grid (which=0: preds, which=1: sorted kept). 1 block/group.
// ---------------------------------------------------------------------------
__global__ void k_grid(int which) {
    int g = blockIdx.x;
    int e = g & 1;
    int CX, CY, CZ; gdims(e, CX, CY, CZ);
    int NCELL = CX * CY * CZ;
    int n = which ? g_nn[g] : g_np[g];
    float (*pos)[3] = which ? g_npos[g] : g_ppos[g];
    int* cellid = which ? g_kc[g] : g_pc[g];
    int* start  = which ? g_kstart[g] : g_cstart[g];
    int* list   = which ? g_klist[g] : g_clist[g];

    __shared__ int s_cnt[MAXCELLS];
    __shared__ int s_sum[257];
    int tid = threadIdx.x;
    for (int c = tid; c < NCELL; c += 256) s_cnt[c] = 0;
    __syncthreads();

    float fx = CX / 25.0f, fy = CY / 25.0f, fz = CZ / 3.0f;
    for (int i = tid; i < n; i += 256) {
        int cx = min(max((int)(pos[i][0] * fx), 0), CX - 1);
        int cy = min(max((int)(pos[i][1] * fy), 0), CY - 1);
        int cz = min(max((int)(pos[i][2] * fz), 0), CZ - 1);
        int c = (cx * CY + cy) * CZ + cz;
        cellid[i] = c;
        atomicAdd(&s_cnt[c], 1);
    }
    __syncthreads();

    int chunk = (NCELL + 255) >> 8;
    int lo = tid * chunk, hi = min(lo + chunk, NCELL);
    int acc = 0;
    for (int c = lo; c < hi; c++) acc += s_cnt[c];
    s_sum[tid] = acc;
    __syncthreads();
    if (tid == 0) {
        int r = 0;
        for (int x = 0; x < 256; x++) { int v = s_sum[x]; s_sum[x] = r; r += v; }
        s_sum[256] = r;
    }
    __syncthreads();
    int r = s_sum[tid];
    for (int c = lo; c < hi; c++) { int v = s_cnt[c]; s_cnt[c] = r; start[c] = r; r += v; }
    if (tid == 0) start[NCELL] = s_sum[256];
    __syncthreads();

    for (int i = tid; i < n; i += 256) {
        int c = cellid[i];
        int p = atomicAdd(&s_cnt[c], 1);
        list[p] = i;
    }
}

// ---------------------------------------------------------------------------
// K3/K4: restrain==0 and sel flags via grid neighborhood (key-ordered)
// ---------------------------------------------------------------------------
__global__ void k_res0() {
    int g = blockIdx.y;
    int j = blockIdx.x * blockDim.x + threadIdx.x;
    int Np = g_np[g];
    if (j >= Np) return;
    int e = g & 1;
    int CX, CY, CZ; gdims(e, CX, CY, CZ);
    float D = e ? DIAM1 : DIAM0;
    float S2 = sqr_thresh(D);
    float xj = g_ppos[g][j][0], yj = g_ppos[g][j][1], zj = g_ppos[g][j][2];
    float qj = g_qp[g][j];
    unsigned long long kj = g_key[g][j];
    int c = g_pc[g][j];
    int cz = c % CZ, cy = (c / CZ) % CY, cx = c / (CZ * CY);

    int res = 1;
    for (int ax = max(cx - 1, 0); ax <= min(cx + 1, CX - 1) && res; ax++)
    for (int ay = max(cy - 1, 0); ay <= min(cy + 1, CY - 1) && res; ay++)
    for (int az = max(cz - 1, 0); az <= min(cz + 1, CZ - 1) && res; az++) {
        int cc = (ax * CY + ay) * CZ + az;
        int p1 = g_cstart[g][cc + 1];
        for (int p = g_cstart[g][cc]; p < p1; p++) {
            int i = g_clist[g][p];
            if (g_key[g][i] < kj) {
                float s = dist2(g_qp[g][i], qj,
                                g_ppos[g][i][0], g_ppos[g][i][1], g_ppos[g][i][2],
                                xj, yj, zj);
                if (s < S2) { res = 0; break; }
            }
        }
    }
    g_res0[g][j] = (unsigned char)res;
}

__global__ void k_sel() {
    int g = blockIdx.y;
    int j = blockIdx.x * blockDim.x + threadIdx.x;
    int Np = g_np[g];
    if (j >= Np) return;
    int e = g & 1;
    int CX, CY, CZ; gdims(e, CX, CY, CZ);
    float D = e ? DIAM1 : DIAM0;
    float S2 = sqr_thresh(D);
    float xj = g_ppos[g][j][0], yj = g_ppos[g][j][1], zj = g_ppos[g][j][2];
    float qj = g_qp[g][j];
    unsigned long long kj = g_key[g][j];
    int c = g_pc[g][j];
    int cz = c % CZ, cy = (c / CZ) % CY, cx = c / (CZ * CY);

    int keep = 1;
    for (int ax = max(cx - 1, 0); ax <= min(cx + 1, CX - 1) && keep; ax++)
    for (int ay = max(cy - 1, 0); ay <= min(cy + 1, CY - 1) && keep; ay++)
    for (int az = max(cz - 1, 0); az <= min(cz + 1, CZ - 1) && keep; az++) {
        int cc = (ax * CY + ay) * CZ + az;
        int p1 = g_cstart[g][cc + 1];
        for (int p = g_cstart[g][cc]; p < p1; p++) {
            int i = g_clist[g][p];
            if (g_res0[g][i] && g_key[g][i] < kj) {
                float s = dist2(g_qp[g][i], qj,
                                g_ppos[g][i][0], g_ppos[g][i][1], g_ppos[g][i][2],
                                xj, yj, zj);
                if (s < S2) { keep = 0; break; }
            }
        }
    }
    g_keep[g][j] = (unsigned char)keep;
}

// ---------------------------------------------------------------------------
// K5: compact kept keys (masked order)
// ---------------------------------------------------------------------------
__global__ void k_keptcompact() {
    int g = blockIdx.x;
    int tid = threadIdx.x;
    int lane = tid & 31, w = tid >> 5;
    int Np = g_np[g];
    __shared__ int wt[8];
    __shared__ int base;
    if (tid == 0) base = 0;
    __syncthreads();
    for (int cb = 0; cb < Np; cb += 256) {
        int j = cb + tid;
        int f = (j < Np) ? (int)g_keep[g][j] : 0;
        unsigned bl = __ballot_sync(0xffffffffu, f);
        if (lane == 0) wt[w] = __popc(bl);
        __syncthreads();
        int off = base;
        for (int x = 0; x < w; x++) off += wt[x];
        off += __popc(bl & ((1u << lane) - 1u));
        if (f) g_kkey[g][off] = g_key[g][j];
        __syncthreads();
        if (tid == 0) { int s = 0; for (int x = 0; x < 8; x++) s += wt[x]; base += s; }
        __syncthreads();
    }
    if (tid == 0) g_nk[g] = base;
}

// ---------------------------------------------------------------------------
// K6: sort kept by key ascending (bitonic in shared), gather sorted arrays
// ---------------------------------------------------------------------------
__global__ void k_sortkept() {
    int g = blockIdx.x;
    int n = g_nk[g];
    int tid = threadIdx.x;
    __shared__ unsigned long long sk[4096];

    if (n <= 4096) {
        for (int i = tid; i < 4096; i += 1024) sk[i] = (i < n) ? g_kkey[g][i] : ~0ull;
        __syncthreads();
        for (int k = 2; k <= 4096; k <<= 1)
            for (int j = k >> 1; j > 0; j >>= 1) {
                for (int i = tid; i < 4096; i += 1024) {
                    int l = i ^ j;
                    if (l > i) {
                        unsigned long long a = sk[i], b = sk[l];
                        bool asc = ((i & k) == 0);
                        if ((a > b) == asc) { sk[i] = b; sk[l] = a; }
                    }
                }
                __syncthreads();
            }
        for (int r2 = tid; r2 < n; r2 += 1024) {
            int src = (int)(sk[r2] & 0xffffffffull);
            g_nsrc[g][r2] = src;
            g_npos[g][r2][0] = g_ppos[g][src][0];
            g_npos[g][r2][1] = g_ppos[g][src][1];
            g_npos[g][r2][2] = g_ppos[g][src][2];
            g_nq[g][r2] = g_qp[g][src];
        }
    } else {
        // correctness fallback (rank counting) — never expected with this data
        for (int i = tid; i < n; i += 1024) {
            unsigned long long ki = g_kkey[g][i];
            int rank = 0;
            for (int j2 = 0; j2 < n; j2++) rank += (g_kkey[g][j2] < ki);
            int src = (int)(ki & 0xffffffffull);
            g_nsrc[g][rank] = src;
            g_npos[g][rank][0] = g_ppos[g][src][0];
            g_npos[g][rank][1] = g_ppos[g][src][1];
            g_npos[g][rank][2] = g_ppos[g][src][2];
            g_nq[g][rank] = g_qp[g][src];
        }
    }
    if (tid == 0) g_nn[g] = n;
}

// ---------------------------------------------------------------------------
// K7: match (targets vs preds, targets vs sorted kept) via grid query
// exact argmin-first semantics, order independent
// ---------------------------------------------------------------------------
__device__ __forceinline__ void matchQuery(
    const int* __restrict__ start, const int* __restrict__ list,
    const float (*__restrict__ pos)[3], const float* __restrict__ q,
    float tx, float ty, float tz, float qt, float S2,
    int cx, int cy, int cz, int CX, int CY, int CZ,
    int& anyOut, int& idxOut)
{
    int any = 0;
    float bs = __int_as_float(0x7f800000);  // +inf
    int bi = 0x7fffffff;
    for (int ax = max(cx - 1, 0); ax <= min(cx + 1, CX - 1); ax++)
    for (int ay = max(cy - 1, 0); ay <= min(cy + 1, CY - 1); ay++)
    for (int az = max(cz - 1, 0); az <= min(cz + 1, CZ - 1); az++) {
        int c = (ax * CY + ay) * CZ + az;
        int p1 = start[c + 1];
        for (int p = start[c]; p < p1; p++) {
            int jj = list[p];
            float s = dist2(qt, q[jj], tx, ty, tz, pos[jj][0], pos[jj][1], pos[jj][2]);
            s = fmaxf(s, 0.0f);
            any |= (s < S2);
            if (s < bs) {
                float dn = sqrtf(s), db = sqrtf(bs);
                bi = (dn == db) ? min(bi, jj) : jj;
                bs = s;
            } else if (jj < bi && s <= __fmul_rn(bs, 1.000001f)) {
                if (sqrtf(s) == sqrtf(bs)) bi = jj;
            }
        }
    }
    anyOut = any;
    idxOut = (bi == 0x7fffffff) ? 0 : bi;
}

__global__ void k_match() {
    int g = blockIdx.y;
    int t = blockIdx.x * blockDim.x + threadIdx.x;
    int Nt = g_nt[g];
    if (t >= Nt) return;
    int e = g & 1;
    int CX, CY, CZ; gdims(e, CX, CY, CZ);
    float D = e ? DIAM1 : DIAM0;
    float S2 = sqr_thresh(D);
    float tx = g_tpos[g][t][0], ty = g_tpos[g][t][1], tz = g_tpos[g][t][2];
    float qt = g_qt[g][t];
    float fx = CX / 25.0f, fy = CY / 25.0f, fz = CZ / 3.0f;
    int cx = min(max((int)(tx * fx), 0), CX - 1);
    int cy = min(max((int)(ty * fy), 0), CY - 1);
    int cz = min(max((int)(tz * fz), 0), CZ - 1);

    int any, bi;
    matchQuery(g_cstart[g], g_clist[g], g_ppos[g], g_qp[g],
               tx, ty, tz, qt, S2, cx, cy, cz, CX, CY, CZ, any, bi);
    g_m[g][t] = any; g_piv[g][t] = bi;

    matchQuery(g_kstart[g], g_klist[g], g_npos[g], g_nq[g],
               tx, ty, tz, qt, S2, cx, cy, cz, CX, CY, CZ, any, bi);
    g_mn[g][t] = any; g_pinv[g][t] = bi;
}

// ---------------------------------------------------------------------------
// K8: compact (ti, pi) and (ti_n, pi_n)
// ---------------------------------------------------------------------------
__global__ void k_match_compact() {
    int g = blockIdx.x;
    int tid = threadIdx.x;
    int lane = tid & 31, w = tid >> 5;
    int Nt = g_nt[g];
    __shared__ int wt[8];
    __shared__ int base;

    for (int pass = 0; pass < 2; pass++) {
        if (tid == 0) base = 0;
        __syncthreads();
        for (int cb = 0; cb < Nt; cb += 256) {
            int t = cb + tid;
            int f = 0;
            if (t < Nt) f = pass ? g_mn[g][t] : g_m[g][t];
            unsigned bl = __ballot_sync(0xffffffffu, f != 0);
            if (lane == 0) wt[w] = __popc(bl);
            __syncthreads();
            int off = base;
            for (int x = 0; x < w; x++) off += wt[x];
            off += __popc(bl & ((1u << lane) - 1u));
            if (f) {
                if (pass) { g_tin[g][off] = t; g_pin[g][off] = g_pinv[g][t]; }
                else      { g_ti[g][off]  = t; g_pi[g][off]  = g_piv[g][t]; }
            }
            __syncthreads();
            if (tid == 0) { int s = 0; for (int x = 0; x < 8; x++) s += wt[x]; base += s; }
            __syncthreads();
        }
        if (tid == 0) { if (pass) g_kn[g] = base; else g_k[g] = base; }
        __syncthreads();
    }
}

// ---------------------------------------------------------------------------
// K9: output offsets
// ---------------------------------------------------------------------------
__global__ void k_offsets() {
    long long base = 0;
    for (int g = 0; g < NG; g++) {
        g_base[g] = base;
        long long Np = g_np[g], Nn = g_nn[g], Nt = g_nt[g], K = g_k[g], Kn = g_kn[g];
        base += Np * 4 + Nn * 4 + Nt * 4 + 2 * K + 2 * Kn + Np * 3 + Nn * 3 + Nt * 3;
    }
}

// ---------------------------------------------------------------------------
// K10: write concatenated output
// ---------------------------------------------------------------------------
__global__ void k_write(float* __restrict__ out) {
    int g = blockIdx.y;
    long long base = g_base[g];
    int Np = g_np[g], Nn = g_nn[g], Nt = g_nt[g], K = g_k[g], Kn = g_kn[g];
    int T = Np * 4 + Nn * 4 + Nt * 4 + 2 * K + 2 * Kn + Np * 3 + Nn * 3 + Nt * 3;
    int stride = gridDim.x * blockDim.x;
    for (int idx = blockIdx.x * blockDim.x + threadIdx.x; idx < T; idx += stride) {
        int o = idx;
        float v;
        if (o < Np * 4) { v = g_praw[g][o >> 2][o & 3]; }
        else {
            o -= Np * 4;
            if (o < Nn * 4) { v = g_praw[g][g_nsrc[g][o >> 2]][o & 3]; }
            else {
                o -= Nn * 4;
                if (o < Nt * 4) { v = g_traw[g][o >> 2][o & 3]; }
                else {
                    o -= Nt * 4;
                    if (o < K) { v = (float)g_ti[g][o]; }
                    else {
                        o -= K;
                        if (o < K) { v = (float)g_pi[g][o]; }
                        else {
                            o -= K;
                            if (o < Kn) { v = (float)g_tin[g][o]; }
                            else {
                                o -= Kn;
                                if (o < Kn) { v = (float)g_pin[g][o]; }
                                else {
                                    o -= Kn;
                                    if (o < Np * 3) { v = g_ppos[g][o / 3][o % 3]; }
                                    else {
                                        o -= Np * 3;
                                        if (o < Nn * 3) { v = g_npos[g][o / 3][o % 3]; }
                                        else { o -= Nn * 3; v = g_tpos[g][o / 3][o % 3]; }
                                    }
                                }
                            }
                        }
                    }
                }
            }
        }
        out[base + idx] = v;
    }
}

// ---------------------------------------------------------------------------
// launch
// ---------------------------------------------------------------------------
extern "C" void kernel_launch(void* const* d_in, const int* in_sizes, int n_in,
                              void* d_out, int out_size) {
    const float* pred = (const float*)d_in[0];
    const float* tgt  = (const float*)d_in[1];
    float* out = (float*)d_out;
    (void)in_sizes; (void)n_in; (void)out_size;

    dim3 gidx(32, NG);

    k_compact<<<NG, 256>>>(pred, tgt);
    k_grid<<<NG, 256>>>(0);
    k_res0<<<gidx, 256>>>();
    k_sel<<<gidx, 256>>>();
    k_keptcompact<<<NG, 256>>>();
    k_sortkept<<<NG, 1024>>>();
    k_grid<<<NG, 256>>>(1);
    k_match<<<gidx, 256>>>();
    k_match_compact<<<NG, 256>>>();
    k_offsets<<<1, 1>>>();
    k_write<<<gidx, 256>>>(out);
}